// round 1
// baseline (speedup 1.0000x reference)
#include <cuda_runtime.h>

#define HPX 512
#define WPX 512
#define HW  (HPX*WPX)          // 262144
#define HOB 518                 // r2 output side (512 + 2*4 - 2)
#define HW2 (HOB*HOB)           // 268324

typedef unsigned long long u64;

// ---------------- device scratch (no cudaMalloc allowed) ----------------
__device__ float g_t1raw[32*HW];
__device__ float g_t1   [32*HW];
__device__ float g_t2raw[32*HW];
__device__ float g_xemb [32*HW];
__device__ float g_graw [128*HW];
__device__ float g_r1raw[32*HW];
__device__ float g_r1   [32*HW];
__device__ float g_r2raw[4*HW2];
__device__ float g_wt_e1[4*9*32];
__device__ float g_wt_e2[32*9*32];
__device__ float g_wt_g [4*64*9*32];
__device__ float g_wt_r1[32*9*32];
__device__ float g_wt_r2[32*9*4];
__device__ float g_stats[512];   // e1:[0,64) e2:[64,128) gates:[128,384) r1:[384,448) r2:[448,454)

// ---------------- f32x2 helpers ----------------
__device__ __forceinline__ u64 pack2(float x) {
    unsigned u = __float_as_uint(x);
    u64 r;
    asm("mov.b64 %0, {%1, %2};" : "=l"(r) : "r"(u), "r"(u));
    return r;
}
__device__ __forceinline__ u64 ffma2(u64 a, u64 b, u64 c) {
    u64 d;
    asm("fma.rn.f32x2 %0, %1, %2, %3;" : "=l"(d) : "l"(a), "l"(b), "l"(c));
    return d;
}
__device__ __forceinline__ void unpack2(u64 v, float& lo, float& hi) {
    unsigned a, b;
    asm("mov.b64 {%0, %1}, %2;" : "=r"(a), "=r"(b) : "l"(v));
    lo = __uint_as_float(a); hi = __uint_as_float(b);
}
__device__ __forceinline__ float sigmoidf_(float x) { return 1.f / (1.f + expf(-x)); }

// ---------------- weight transpose/prep: [cout][cin][k] -> [cin*9+k][cout] ----------------
__global__ void prep_weights(const float* __restrict__ we1, const float* __restrict__ we2,
                             const float* __restrict__ wf,  const float* __restrict__ wi,
                             const float* __restrict__ wc,  const float* __restrict__ wo,
                             const float* __restrict__ wr1, const float* __restrict__ wr2)
{
    int idx = blockIdx.x * 256 + threadIdx.x;
    // e1: 32x4x9 -> 1152
    if (idx < 1152) {
        int cout = idx % 32, t = idx / 32, k = t % 9, cin = t / 9;
        g_wt_e1[idx] = we1[cout*4*9 + cin*9 + k];
        return;
    }
    idx -= 1152;
    // e2: 9216
    if (idx < 9216) {
        int cout = idx % 32, t = idx / 32, k = t % 9, cin = t / 9;
        g_wt_e2[idx] = we2[cout*32*9 + cin*9 + k];
        return;
    }
    idx -= 9216;
    // gates: 4 * 18432
    if (idx < 4*18432) {
        int g = idx / 18432, d = idx % 18432;
        int cout = d % 32, t = d / 32, k = t % 9, cin = t / 9;
        const float* src = (g == 0) ? wf : (g == 1) ? wi : (g == 2) ? wc : wo;
        g_wt_g[idx] = src[cout*64*9 + cin*9 + k];
        return;
    }
    idx -= 4*18432;
    // r1: 9216
    if (idx < 9216) {
        int cout = idx % 32, t = idx / 32, k = t % 9, cin = t / 9;
        g_wt_r1[idx] = wr1[cout*32*9 + cin*9 + k];
        return;
    }
    idx -= 9216;
    // r2 padded to 4 couts: 32*9*4 = 1152
    if (idx < 1152) {
        int cout = idx % 4, t = idx / 4, k = t % 9, cin = t / 9;
        g_wt_r2[idx] = (cout < 3) ? wr2[cout*32*9 + cin*9 + k] : 0.f;
        return;
    }
}

__global__ void zero_stats_kernel() {
    if (threadIdx.x < 512) g_stats[threadIdx.x] = 0.f;
}

// ---------------- generic 3x3 conv, f32x2-packed accumulators ----------------
// Block: 16x16 threads, output tile 32x16 (2 pixels per thread, x and x+16).
// smem: weights [CIN*9][COUT], then input tile (TH+2)x(TW+2) per cin.
template<int CIN, int COUT>
__global__ void __launch_bounds__(256)
conv3x3_kernel(const float* __restrict__ inA, const float* __restrict__ inB, int csplit,
               const float* __restrict__ wt, float* __restrict__ out,
               int H, int W, int pad, int HO, int WO)
{
    constexpr int TW = 32, TH = 16, TPW = TW + 2, TPH = TH + 2;
    constexpr int C2 = COUT / 2;
    extern __shared__ float smem[];
    float* ws   = smem;                  // CIN*9*COUT
    float* tile = smem + CIN*9*COUT;     // TPH*TPW

    const int tx = threadIdx.x, ty = threadIdx.y;
    const int tid = ty * 16 + tx;

    const float* wsrc = wt + (size_t)blockIdx.z * (CIN*9*COUT);
    for (int i = tid; i < CIN*9*COUT; i += 256) ws[i] = wsrc[i];

    const int gx = blockIdx.x * TW, gy = blockIdx.y * TH;
    const int oy = gy + ty;
    const int ox0 = gx + tx, ox1 = ox0 + 16;

    u64 accA[C2], accB[C2];
#pragma unroll
    for (int p = 0; p < C2; p++) { accA[p] = 0ull; accB[p] = 0ull; }

    for (int cin = 0; cin < CIN; ++cin) {
        __syncthreads();
        const float* ip = (cin < csplit) ? (inA + (size_t)cin * H * W)
                                         : (inB + (size_t)(cin - csplit) * H * W);
        for (int i = tid; i < TPH * TPW; i += 256) {
            int r = i / TPW, c = i % TPW;
            int iy = gy - pad + r, ix = gx - pad + c;
            tile[i] = (iy >= 0 && iy < H && ix >= 0 && ix < W) ? ip[(size_t)iy * W + ix] : 0.f;
        }
        __syncthreads();

        float a[9], b[9];
#pragma unroll
        for (int ky = 0; ky < 3; ky++)
#pragma unroll
            for (int kx = 0; kx < 3; kx++) {
                a[ky*3+kx] = tile[(ty + ky) * TPW + tx + kx];
                b[ky*3+kx] = tile[(ty + ky) * TPW + tx + 16 + kx];
            }

        const u64* w2 = (const u64*)(ws + cin * 9 * COUT);
#pragma unroll
        for (int k = 0; k < 9; k++) {
            u64 va = pack2(a[k]);
            u64 vb = pack2(b[k]);
#pragma unroll
            for (int p = 0; p < C2; p++) {
                u64 w = w2[k * C2 + p];
                accA[p] = ffma2(va, w, accA[p]);
                accB[p] = ffma2(vb, w, accB[p]);
            }
        }
    }

    float* ob = out + (size_t)blockIdx.z * COUT * HO * WO;
    if (oy < HO) {
#pragma unroll
        for (int p = 0; p < C2; p++) {
            float lo, hi;
            if (ox0 < WO) {
                unpack2(accA[p], lo, hi);
                ob[(size_t)(2*p  ) * HO * WO + (size_t)oy * WO + ox0] = lo;
                ob[(size_t)(2*p+1) * HO * WO + (size_t)oy * WO + ox0] = hi;
            }
            if (ox1 < WO) {
                unpack2(accB[p], lo, hi);
                ob[(size_t)(2*p  ) * HO * WO + (size_t)oy * WO + ox1] = lo;
                ob[(size_t)(2*p+1) * HO * WO + (size_t)oy * WO + ox1] = hi;
            }
        }
    }
}

// ---------------- per-channel sum / sumsq reduction ----------------
__global__ void stats_kernel(const float* __restrict__ buf, float* __restrict__ stats, int n)
{
    int c = blockIdx.x;
    const float* p = buf + (size_t)c * n;
    int base = blockIdx.y * 8192;
    float s = 0.f, q = 0.f;
    int lim = base + 8192; if (lim > n) lim = n;
    for (int i = base + threadIdx.x; i < lim; i += 256) {
        float v = p[i];
        s += v; q += v * v;
    }
#pragma unroll
    for (int o = 16; o; o >>= 1) {
        s += __shfl_down_sync(0xFFFFFFFFu, s, o);
        q += __shfl_down_sync(0xFFFFFFFFu, q, o);
    }
    __shared__ float ss[8], qq[8];
    int w = threadIdx.x >> 5, l = threadIdx.x & 31;
    if (l == 0) { ss[w] = s; qq[w] = q; }
    __syncthreads();
    if (threadIdx.x == 0) {
        float S = 0.f, Q = 0.f;
        for (int i = 0; i < 8; i++) { S += ss[i]; Q += qq[i]; }
        atomicAdd(&stats[2*c],   S);
        atomicAdd(&stats[2*c+1], Q);
    }
}

// ---------------- BN (+optional relu) ----------------
__global__ void finalize_kernel(const float* __restrict__ raw, const float* __restrict__ stats,
                                float* __restrict__ out, int n, int relu)
{
    int idx = blockIdx.x * 256 + threadIdx.x;
    int c = idx / n;
    float invn = 1.f / (float)n;
    float m  = stats[2*c] * invn;
    float var = stats[2*c+1] * invn - m * m;
    float v = (raw[idx] - m) * rsqrtf(var + 1e-5f);
    out[idx] = relu ? fmaxf(v, 0.f) : v;
}

// ---------------- LSTM elementwise ----------------
__global__ void lstm_kernel(const float* __restrict__ prev_c,
                            float* __restrict__ out_c, float* __restrict__ out_h)
{
    int idx = blockIdx.x * 256 + threadIdx.x;   // over 32*HW
    int c = idx / HW;
    const int CHW = 32 * HW;
    const float invn = 1.f / (float)HW;
    const float* st = g_stats + 128;

    float g[4];
#pragma unroll
    for (int gi = 0; gi < 4; gi++) {
        int ch = gi * 32 + c;
        float m  = st[2*ch] * invn;
        float var = st[2*ch+1] * invn - m * m;
        g[gi] = (g_graw[(size_t)gi * CHW + idx] - m) * rsqrtf(var + 1e-5f);
    }
    float f  = sigmoidf_(g[0]);
    float it = sigmoidf_(g[1]);
    float ct = tanhf(g[2]);
    float ot = sigmoidf_(g[3]);
    float nc = prev_c[idx] * f + it * ct;
    out_c[idx] = nc;
    out_h[idx] = tanhf(nc) * ot;
}

// ---------------- patch gather + per-channel dot ----------------
__global__ void gather_kernel(const int* __restrict__ holes,
                              const float* __restrict__ woil, const float* __restrict__ boil,
                              const float* __restrict__ wwat, const float* __restrict__ bwat,
                              const float* __restrict__ wgas, const float* __restrict__ bgas,
                              float* __restrict__ res)
{
    int nidx = threadIdx.x;
    if (nidx >= 256) return;
    int hx = holes[2*nidx], hy = holes[2*nidx+1];
    const float* wv[3] = { woil, wwat, wgas };
    float bv[3] = { boil[0], bwat[0], bgas[0] };
    const float invn = 1.f / (float)HW2;
    const float* st = g_stats + 448;
    for (int c = 0; c < 3; c++) {
        float m  = st[2*c] * invn;
        float var = st[2*c+1] * invn - m * m;
        float inv = rsqrtf(var + 1e-5f);
        float s = bv[c];
        for (int i = 0; i < 3; i++)
            for (int j = 0; j < 3; j++) {
                float v = g_r2raw[(size_t)c * HW2 + (size_t)(hx + 3 + i) * HOB + (hy + 3 + j)];
                s += wv[c][i*3+j] * ((v - m) * inv);
            }
        res[nidx*3 + c] = s;
    }
}

// ---------------- launch ----------------
extern "C" void kernel_launch(void* const* d_in, const int* in_sizes, int n_in,
                              void* d_out, int out_size)
{
    const float* x      = (const float*)d_in[0];
    const float* prev_c = (const float*)d_in[1];
    const float* prev_h = (const float*)d_in[2];
    const int*   holes  = (const int*)d_in[3];
    const float* w_e1   = (const float*)d_in[4];
    const float* w_e2   = (const float*)d_in[5];
    const float* w_f    = (const float*)d_in[6];
    const float* w_i    = (const float*)d_in[7];
    const float* w_c    = (const float*)d_in[8];
    const float* w_o    = (const float*)d_in[9];
    const float* w_r1   = (const float*)d_in[10];
    const float* w_r2   = (const float*)d_in[11];
    const float* w_oil  = (const float*)d_in[12];
    const float* b_oil  = (const float*)d_in[13];
    const float* w_wat  = (const float*)d_in[14];
    const float* b_wat  = (const float*)d_in[15];
    const float* w_gas  = (const float*)d_in[16];
    const float* b_gas  = (const float*)d_in[17];
    float* out = (float*)d_out;

    // device-global addresses
    float *t1raw, *t1, *t2raw, *xemb, *graw, *r1raw, *r1, *r2raw;
    float *wt_e1, *wt_e2, *wt_g, *wt_r1, *wt_r2, *stats;
    cudaGetSymbolAddress((void**)&t1raw, g_t1raw);
    cudaGetSymbolAddress((void**)&t1,    g_t1);
    cudaGetSymbolAddress((void**)&t2raw, g_t2raw);
    cudaGetSymbolAddress((void**)&xemb,  g_xemb);
    cudaGetSymbolAddress((void**)&graw,  g_graw);
    cudaGetSymbolAddress((void**)&r1raw, g_r1raw);
    cudaGetSymbolAddress((void**)&r1,    g_r1);
    cudaGetSymbolAddress((void**)&r2raw, g_r2raw);
    cudaGetSymbolAddress((void**)&wt_e1, g_wt_e1);
    cudaGetSymbolAddress((void**)&wt_e2, g_wt_e2);
    cudaGetSymbolAddress((void**)&wt_g,  g_wt_g);
    cudaGetSymbolAddress((void**)&wt_r1, g_wt_r1);
    cudaGetSymbolAddress((void**)&wt_r2, g_wt_r2);
    cudaGetSymbolAddress((void**)&stats, g_stats);

    const int SM_4_32  = (4*9*32  + 18*34) * 4;
    const int SM_32_32 = (32*9*32 + 18*34) * 4;
    const int SM_64_32 = (64*9*32 + 18*34) * 4;
    const int SM_32_4  = (32*9*4  + 18*34) * 4;
    cudaFuncSetAttribute((const void*)conv3x3_kernel<4,32>,  cudaFuncAttributeMaxDynamicSharedMemorySize, SM_4_32);
    cudaFuncSetAttribute((const void*)conv3x3_kernel<32,32>, cudaFuncAttributeMaxDynamicSharedMemorySize, SM_32_32);
    cudaFuncSetAttribute((const void*)conv3x3_kernel<64,32>, cudaFuncAttributeMaxDynamicSharedMemorySize, SM_64_32);
    cudaFuncSetAttribute((const void*)conv3x3_kernel<32,4>,  cudaFuncAttributeMaxDynamicSharedMemorySize, SM_32_4);

    dim3 thr(16, 16);
    dim3 grid512(512/32, 512/16, 1);       // 16 x 32
    dim3 gridG  (512/32, 512/16, 4);
    dim3 gridR2 ((HOB + 31)/32, (HOB + 15)/16, 1);   // 17 x 33

    zero_stats_kernel<<<1, 512>>>();
    prep_weights<<<(94464 + 255)/256, 256>>>(w_e1, w_e2, w_f, w_i, w_c, w_o, w_r1, w_r2);

    // e1: x (4ch) -> t1raw ; BN+relu -> t1
    conv3x3_kernel<4,32><<<grid512, thr, SM_4_32>>>(x, x, 4, wt_e1, t1raw, 512, 512, 1, 512, 512);
    stats_kernel<<<dim3(32, 32), 256>>>(t1raw, stats + 0, HW);
    finalize_kernel<<<32*HW/256, 256>>>(t1raw, stats + 0, t1, HW, 1);

    // e2: t1 -> t2raw ; BN -> xemb
    conv3x3_kernel<32,32><<<grid512, thr, SM_32_32>>>(t1, t1, 32, wt_e2, t2raw, 512, 512, 1, 512, 512);
    stats_kernel<<<dim3(32, 32), 256>>>(t2raw, stats + 64, HW);
    finalize_kernel<<<32*HW/256, 256>>>(t2raw, stats + 64, xemb, HW, 0);

    // gates: [prev_h ; xemb] (64ch) -> graw (4 x 32ch), one launch over z
    conv3x3_kernel<64,32><<<gridG, thr, SM_64_32>>>(prev_h, xemb, 32, wt_g, graw, 512, 512, 1, 512, 512);
    stats_kernel<<<dim3(128, 32), 256>>>(graw, stats + 128, HW);

    // LSTM elementwise -> out[0:32HW]=next_c, out[32HW:64HW]=next_h
    lstm_kernel<<<32*HW/256, 256>>>(prev_c, out, out + 32*HW);

    // r1: next_h -> r1raw ; BN+relu -> r1
    conv3x3_kernel<32,32><<<grid512, thr, SM_32_32>>>(out + 32*HW, out + 32*HW, 32, wt_r1, r1raw, 512, 512, 1, 512, 512);
    stats_kernel<<<dim3(32, 32), 256>>>(r1raw, stats + 384, HW);
    finalize_kernel<<<32*HW/256, 256>>>(r1raw, stats + 384, r1, HW, 1);

    // r2: r1 -> r2raw (3+1 ch @ 518x518, pad 4)
    conv3x3_kernel<32,4><<<gridR2, thr, SM_32_4>>>(r1, r1, 32, wt_r2, r2raw, 512, 512, 4, HOB, HOB);
    stats_kernel<<<dim3(3, (HW2 + 8191)/8192), 256>>>(r2raw, stats + 448, HW2);

    // gather + dot -> out tail
    gather_kernel<<<1, 256>>>(holes, w_oil, b_oil, w_wat, b_wat, w_gas, b_gas, out + 64*HW);
}

// round 2
// speedup vs baseline: 1.0075x; 1.0075x over previous
#include <cuda_runtime.h>

#define HPX 512
#define WPX 512
#define HW  (HPX*WPX)           // 262144 = 2^18
#define HOB 518                 // r2 output side (512 + 2*4 - 2)
#define HW2 (HOB*HOB)           // 268324

typedef unsigned long long u64;

// ---------------- device scratch (no cudaMalloc allowed) ----------------
__device__ float g_t1raw[32*HW];
__device__ float g_t2raw[32*HW];
__device__ float g_graw [128*HW];
__device__ float g_r1raw[32*HW];
__device__ float g_r2raw[4*HW2];
__device__ float g_wt_e1[4*9*32];
__device__ float g_wt_e2[32*9*32];
__device__ float g_wt_g [4*64*9*32];
__device__ float g_wt_r1[32*9*32];
__device__ float g_wt_r2[32*9*4];
__device__ float  g_stats[512];    // e1:[0,64) e2:[64,128) gates:[128,384) r1:[384,448) r2:[448,456)
__device__ float2 g_params[256];   // e1:0 e2:32 gates:64 r1:192 r2:224   (scale, bias)

// ---------------- f32x2 helpers ----------------
__device__ __forceinline__ u64 pack2(float x) {
    unsigned u = __float_as_uint(x);
    u64 r;
    asm("mov.b64 %0, {%1, %2};" : "=l"(r) : "r"(u), "r"(u));
    return r;
}
__device__ __forceinline__ u64 ffma2(u64 a, u64 b, u64 c) {
    u64 d;
    asm("fma.rn.f32x2 %0, %1, %2, %3;" : "=l"(d) : "l"(a), "l"(b), "l"(c));
    return d;
}
__device__ __forceinline__ void unpack2(u64 v, float& lo, float& hi) {
    unsigned a, b;
    asm("mov.b64 {%0, %1}, %2;" : "=r"(a), "=r"(b) : "l"(v));
    lo = __uint_as_float(a); hi = __uint_as_float(b);
}
__device__ __forceinline__ float sigmoidf_(float x) { return 1.f / (1.f + expf(-x)); }

// ---------------- weight transpose/prep: [cout][cin][k] -> [cin*9+k][cout] ----------------
__global__ void prep_weights(const float* __restrict__ we1, const float* __restrict__ we2,
                             const float* __restrict__ wf,  const float* __restrict__ wi,
                             const float* __restrict__ wc,  const float* __restrict__ wo,
                             const float* __restrict__ wr1, const float* __restrict__ wr2)
{
    int idx = blockIdx.x * 256 + threadIdx.x;
    if (idx < 1152) {
        int cout = idx % 32, t = idx / 32, k = t % 9, cin = t / 9;
        g_wt_e1[idx] = we1[cout*4*9 + cin*9 + k];
        return;
    }
    idx -= 1152;
    if (idx < 9216) {
        int cout = idx % 32, t = idx / 32, k = t % 9, cin = t / 9;
        g_wt_e2[idx] = we2[cout*32*9 + cin*9 + k];
        return;
    }
    idx -= 9216;
    if (idx < 4*18432) {
        int g = idx / 18432, d = idx % 18432;
        int cout = d % 32, t = d / 32, k = t % 9, cin = t / 9;
        const float* src = (g == 0) ? wf : (g == 1) ? wi : (g == 2) ? wc : wo;
        g_wt_g[idx] = src[cout*64*9 + cin*9 + k];
        return;
    }
    idx -= 4*18432;
    if (idx < 9216) {
        int cout = idx % 32, t = idx / 32, k = t % 9, cin = t / 9;
        g_wt_r1[idx] = wr1[cout*32*9 + cin*9 + k];
        return;
    }
    idx -= 9216;
    if (idx < 1152) {
        int cout = idx % 4, t = idx / 4, k = t % 9, cin = t / 9;
        g_wt_r2[idx] = (cout < 3) ? wr2[cout*32*9 + cin*9 + k] : 0.f;
        return;
    }
}

__global__ void zero_stats_kernel() {
    g_stats[threadIdx.x] = 0.f;
}

// stats (sum, sumsq) -> params (scale, bias): y = x*scale + bias == (x-mean)*rsqrt(var+eps)
__global__ void make_params(const float* __restrict__ stats, float2* __restrict__ params,
                            int nch, float invn)
{
    int c = threadIdx.x;
    if (c >= nch) return;
    float m   = stats[2*c] * invn;
    float var = stats[2*c+1] * invn - m * m;
    float sc  = rsqrtf(var + 1e-5f);
    params[c] = make_float2(sc, -m * sc);
}

// ---------------- generic 3x3 conv, f32x2 accumulators, fused input-BN + output-stats --------
// Block 16x16 threads, output tile 32x16 (2 px/thread: x and x+16).
// smem: weights [CIN*9][COUT], then CHUNK input tiles (TH+2)x(TW+2).
template<int CIN, int COUT, int CHUNK>
__global__ void __launch_bounds__(256, 2)
conv3x3_v2(const float* __restrict__ inA, const float* __restrict__ inB, int csplit,
           const float2* __restrict__ prmA, const float2* __restrict__ prmB,
           int reluA, int reluB,
           const float* __restrict__ wt, float* __restrict__ out, float* __restrict__ statsOut,
           int H, int W, int pad, int HO, int WO)
{
    constexpr int TW = 32, TH = 16, TPW = TW + 2, TPH = TH + 2;
    constexpr int C2 = COUT / 2;
    static_assert(C2 % 2 == 0, "C2 must be even for 128b weight loads");
    extern __shared__ float smem[];
    float* ws   = smem;                         // CIN*9*COUT
    float* tile = smem + CIN*9*COUT;            // CHUNK * TPH*TPW
    __shared__ float sstat[2*COUT];

    const int tx = threadIdx.x, ty = threadIdx.y;
    const int tid = ty * 16 + tx;

    const float* wsrc = wt + (size_t)blockIdx.z * (CIN*9*COUT);
    for (int i = tid; i < CIN*9*COUT; i += 256) ws[i] = wsrc[i];
    if (tid < 2*COUT) sstat[tid] = 0.f;

    const int gx = blockIdx.x * TW, gy = blockIdx.y * TH;
    const int oy = gy + ty;
    const int ox0 = gx + tx, ox1 = ox0 + 16;

    u64 accA[C2], accB[C2];
#pragma unroll
    for (int p = 0; p < C2; p++) { accA[p] = 0ull; accB[p] = 0ull; }

    for (int cb = 0; cb < CIN; cb += CHUNK) {
        __syncthreads();
        // fill CHUNK tiles (with per-channel BN applied on load)
        for (int cc = 0; cc < CHUNK; ++cc) {
            int cin = cb + cc;
            bool isA = cin < csplit;
            const float* ip = isA ? (inA + (size_t)cin * H * W)
                                  : (inB + (size_t)(cin - csplit) * H * W);
            const float2* prm = isA ? prmA : prmB;
            int pidx = isA ? cin : (cin - csplit);
            float sc = 1.f, bi = 0.f;
            int rl = isA ? reluA : reluB;
            if (prm) { float2 p = prm[pidx]; sc = p.x; bi = p.y; }
            float* tb = tile + cc * TPH * TPW;
            for (int i = tid; i < TPH * TPW; i += 256) {
                int r = i / TPW, c = i % TPW;
                int iy = gy - pad + r, ix = gx - pad + c;
                float v = 0.f;
                if (iy >= 0 && iy < H && ix >= 0 && ix < W) {
                    v = ip[(size_t)iy * W + ix];
                    v = v * sc + bi;
                    if (rl) v = fmaxf(v, 0.f);
                }
                tb[i] = v;
            }
        }
        __syncthreads();

        for (int cc = 0; cc < CHUNK; ++cc) {
            const float* tb = tile + cc * TPH * TPW;
            float a[9], b[9];
#pragma unroll
            for (int ky = 0; ky < 3; ky++)
#pragma unroll
                for (int kx = 0; kx < 3; kx++) {
                    a[ky*3+kx] = tb[(ty + ky) * TPW + tx + kx];
                    b[ky*3+kx] = tb[(ty + ky) * TPW + tx + 16 + kx];
                }
            const u64* w2 = (const u64*)(ws + (cb + cc) * 9 * COUT);
#pragma unroll
            for (int k = 0; k < 9; k++) {
                u64 va = pack2(a[k]);
                u64 vb = pack2(b[k]);
                const ulonglong2* w4 = (const ulonglong2*)(w2 + k * C2);
#pragma unroll
                for (int p2 = 0; p2 < C2/2; p2++) {
                    ulonglong2 w = w4[p2];
                    accA[2*p2  ] = ffma2(va, w.x, accA[2*p2  ]);
                    accB[2*p2  ] = ffma2(vb, w.x, accB[2*p2  ]);
                    accA[2*p2+1] = ffma2(va, w.y, accA[2*p2+1]);
                    accB[2*p2+1] = ffma2(vb, w.y, accB[2*p2+1]);
                }
            }
        }
    }

    // ---- epilogue: store + fused per-channel (sum, sumsq) ----
    float* ob = out + (size_t)blockIdx.z * COUT * HO * WO;
    float* so = statsOut + blockIdx.z * 2 * COUT;
    const bool vA = (oy < HO) && (ox0 < WO);
    const bool vB = (oy < HO) && (ox1 < WO);
    const size_t row = (size_t)oy * WO;
#pragma unroll
    for (int p = 0; p < C2; p++) {
        float a0, a1, b0, b1;
        unpack2(accA[p], a0, a1);
        unpack2(accB[p], b0, b1);
        if (vA) {
            ob[(size_t)(2*p  ) * HO * WO + row + ox0] = a0;
            ob[(size_t)(2*p+1) * HO * WO + row + ox0] = a1;
        }
        if (vB) {
            ob[(size_t)(2*p  ) * HO * WO + row + ox1] = b0;
            ob[(size_t)(2*p+1) * HO * WO + row + ox1] = b1;
        }
        float s0 = (vA ? a0 : 0.f) + (vB ? b0 : 0.f);
        float q0 = (vA ? a0*a0 : 0.f) + (vB ? b0*b0 : 0.f);
        float s1 = (vA ? a1 : 0.f) + (vB ? b1 : 0.f);
        float q1 = (vA ? a1*a1 : 0.f) + (vB ? b1*b1 : 0.f);
#pragma unroll
        for (int o = 16; o; o >>= 1) {
            s0 += __shfl_down_sync(0xFFFFFFFFu, s0, o);
            q0 += __shfl_down_sync(0xFFFFFFFFu, q0, o);
            s1 += __shfl_down_sync(0xFFFFFFFFu, s1, o);
            q1 += __shfl_down_sync(0xFFFFFFFFu, q1, o);
        }
        if ((tid & 31) == 0) {
            atomicAdd(&sstat[4*p  ], s0);
            atomicAdd(&sstat[4*p+1], q0);
            atomicAdd(&sstat[4*p+2], s1);
            atomicAdd(&sstat[4*p+3], q1);
        }
    }
    __syncthreads();
    if (tid < 2*COUT) atomicAdd(&so[tid], sstat[tid]);
}

// ---------------- LSTM elementwise (reads raw gates + BN params) ----------------
__global__ void lstm_kernel(const float* __restrict__ prev_c, const float2* __restrict__ prm,
                            float* __restrict__ out_c, float* __restrict__ out_h)
{
    int idx = blockIdx.x * 256 + threadIdx.x;   // over 32*HW
    int c = idx >> 18;                          // HW = 2^18
    const int CHW = 32 * HW;

    float g[4];
#pragma unroll
    for (int gi = 0; gi < 4; gi++) {
        float2 p = prm[gi*32 + c];
        g[gi] = g_graw[(size_t)gi * CHW + idx] * p.x + p.y;
    }
    float f  = sigmoidf_(g[0]);
    float it = sigmoidf_(g[1]);
    float ct = tanhf(g[2]);
    float ot = sigmoidf_(g[3]);
    float nc = prev_c[idx] * f + it * ct;
    out_c[idx] = nc;
    out_h[idx] = tanhf(nc) * ot;
}

// ---------------- patch gather + per-channel dot ----------------
__global__ void gather_kernel(const int* __restrict__ holes,
                              const float* __restrict__ woil, const float* __restrict__ boil,
                              const float* __restrict__ wwat, const float* __restrict__ bwat,
                              const float* __restrict__ wgas, const float* __restrict__ bgas,
                              const float2* __restrict__ prm,
                              float* __restrict__ res)
{
    int nidx = threadIdx.x;
    if (nidx >= 256) return;
    int hx = holes[2*nidx], hy = holes[2*nidx+1];
    const float* wv[3] = { woil, wwat, wgas };
    float bv[3] = { boil[0], bwat[0], bgas[0] };
    for (int c = 0; c < 3; c++) {
        float2 p = prm[c];
        float s = bv[c];
        for (int i = 0; i < 3; i++)
            for (int j = 0; j < 3; j++) {
                float v = g_r2raw[(size_t)c * HW2 + (size_t)(hx + 3 + i) * HOB + (hy + 3 + j)];
                s += wv[c][i*3+j] * (v * p.x + p.y);
            }
        res[nidx*3 + c] = s;
    }
}

// ---------------- launch ----------------
extern "C" void kernel_launch(void* const* d_in, const int* in_sizes, int n_in,
                              void* d_out, int out_size)
{
    const float* x      = (const float*)d_in[0];
    const float* prev_c = (const float*)d_in[1];
    const float* prev_h = (const float*)d_in[2];
    const int*   holes  = (const int*)d_in[3];
    const float* w_e1   = (const float*)d_in[4];
    const float* w_e2   = (const float*)d_in[5];
    const float* w_f    = (const float*)d_in[6];
    const float* w_i    = (const float*)d_in[7];
    const float* w_c    = (const float*)d_in[8];
    const float* w_o    = (const float*)d_in[9];
    const float* w_r1   = (const float*)d_in[10];
    const float* w_r2   = (const float*)d_in[11];
    const float* w_oil  = (const float*)d_in[12];
    const float* b_oil  = (const float*)d_in[13];
    const float* w_wat  = (const float*)d_in[14];
    const float* b_wat  = (const float*)d_in[15];
    const float* w_gas  = (const float*)d_in[16];
    const float* b_gas  = (const float*)d_in[17];
    float* out = (float*)d_out;

    float *t1raw, *t2raw, *graw, *r1raw, *r2raw;
    float *wt_e1, *wt_e2, *wt_g, *wt_r1, *wt_r2, *stats;
    float2 *params;
    cudaGetSymbolAddress((void**)&t1raw, g_t1raw);
    cudaGetSymbolAddress((void**)&t2raw, g_t2raw);
    cudaGetSymbolAddress((void**)&graw,  g_graw);
    cudaGetSymbolAddress((void**)&r1raw, g_r1raw);
    cudaGetSymbolAddress((void**)&r2raw, g_r2raw);
    cudaGetSymbolAddress((void**)&wt_e1, g_wt_e1);
    cudaGetSymbolAddress((void**)&wt_e2, g_wt_e2);
    cudaGetSymbolAddress((void**)&wt_g,  g_wt_g);
    cudaGetSymbolAddress((void**)&wt_r1, g_wt_r1);
    cudaGetSymbolAddress((void**)&wt_r2, g_wt_r2);
    cudaGetSymbolAddress((void**)&stats, g_stats);
    cudaGetSymbolAddress((void**)&params, g_params);

    const int SM_E1 = (4*9*32  + 4*18*34) * 4;     // 14400
    const int SM_32 = (32*9*32 + 8*18*34) * 4;     // 56448
    const int SM_G  = (64*9*32 + 8*18*34) * 4;     // 93312
    const int SM_R2 = (32*9*4  + 8*18*34) * 4;     // 24192
    cudaFuncSetAttribute((const void*)conv3x3_v2<4,32,4>,  cudaFuncAttributeMaxDynamicSharedMemorySize, SM_E1);
    cudaFuncSetAttribute((const void*)conv3x3_v2<32,32,8>, cudaFuncAttributeMaxDynamicSharedMemorySize, SM_32);
    cudaFuncSetAttribute((const void*)conv3x3_v2<64,32,8>, cudaFuncAttributeMaxDynamicSharedMemorySize, SM_G);
    cudaFuncSetAttribute((const void*)conv3x3_v2<32,4,8>,  cudaFuncAttributeMaxDynamicSharedMemorySize, SM_R2);

    dim3 thr(16, 16);
    dim3 grid512(512/32, 512/16, 1);       // 16 x 32
    dim3 gridG  (512/32, 512/16, 4);
    dim3 gridR2 ((HOB + 31)/32, (HOB + 15)/16, 1);   // 17 x 33

    zero_stats_kernel<<<1, 512>>>();
    prep_weights<<<(94464 + 255)/256, 256>>>(w_e1, w_e2, w_f, w_i, w_c, w_o, w_r1, w_r2);

    // e1: x (4ch, raw) -> t1raw (+stats)
    conv3x3_v2<4,32,4><<<grid512, thr, SM_E1>>>(x, x, 4, nullptr, nullptr, 0, 0,
                                                wt_e1, t1raw, stats + 0, 512, 512, 1, 512, 512);
    make_params<<<1, 32>>>(stats + 0, params + 0, 32, 1.f / (float)HW);

    // e2: relu(BN(t1raw)) -> t2raw (+stats)
    conv3x3_v2<32,32,8><<<grid512, thr, SM_32>>>(t1raw, t1raw, 32, params + 0, params + 0, 1, 1,
                                                 wt_e2, t2raw, stats + 64, 512, 512, 1, 512, 512);
    make_params<<<1, 32>>>(stats + 64, params + 32, 32, 1.f / (float)HW);

    // gates: [prev_h (raw) ; BN(t2raw)] -> graw (4 x 32ch over z) (+stats)
    conv3x3_v2<64,32,8><<<gridG, thr, SM_G>>>(prev_h, t2raw, 32, nullptr, params + 32, 0, 0,
                                              wt_g, graw, stats + 128, 512, 512, 1, 512, 512);
    make_params<<<1, 128>>>(stats + 128, params + 64, 128, 1.f / (float)HW);

    // LSTM -> out[0:32HW]=next_c, out[32HW:64HW]=next_h
    lstm_kernel<<<32*HW/256, 256>>>(prev_c, params + 64, out, out + 32*HW);

    // r1: next_h (raw) -> r1raw (+stats)
    conv3x3_v2<32,32,8><<<grid512, thr, SM_32>>>(out + 32*HW, out + 32*HW, 32, nullptr, nullptr, 0, 0,
                                                 wt_r1, r1raw, stats + 384, 512, 512, 1, 512, 512);
    make_params<<<1, 32>>>(stats + 384, params + 192, 32, 1.f / (float)HW);

    // r2: relu(BN(r1raw)) -> r2raw (3+1 ch @ 518x518, pad 4) (+stats)
    conv3x3_v2<32,4,8><<<gridR2, thr, SM_R2>>>(r1raw, r1raw, 32, params + 192, params + 192, 1, 1,
                                               wt_r2, r2raw, stats + 448, 512, 512, 4, HOB, HOB);
    make_params<<<1, 32>>>(stats + 448, params + 224, 4, 1.f / (float)HW2);

    // gather + dot -> out tail
    gather_kernel<<<1, 256>>>(holes, w_oil, b_oil, w_wat, b_wat, w_gas, b_gas, params + 224, out + 64*HW);
}

// round 3
// speedup vs baseline: 1.0602x; 1.0522x over previous
#include <cuda_runtime.h>

#define HPX 512
#define WPX 512
#define HW  (HPX*WPX)           // 262144 = 2^18
#define HOB 518                 // r2 output side (512 + 2*4 - 2)
#define HW2 (HOB*HOB)           // 268324

typedef unsigned long long u64;

// ---------------- device scratch (no cudaMalloc allowed) ----------------
__device__ float g_t1raw[32*HW];
__device__ float g_t2raw[32*HW];
__device__ float g_graw [128*HW];
__device__ float g_r1raw[32*HW];
__device__ float g_r2raw[4*HW2];
__device__ float g_wt_e1[4*9*32];
__device__ float g_wt_e2[32*9*32];
__device__ float g_wt_g [4*64*9*32];
__device__ float g_wt_r1[32*9*32];
__device__ float g_wt_r2[32*9*4];
__device__ float  g_stats[512];    // e1:[0,64) e2:[64,128) gates:[128,384) r1:[384,448) r2:[448,456)
__device__ float2 g_params[256];   // e1:0 e2:32 gates:64 r1:192 r2:224   (scale, bias)

// ---------------- f32x2 helpers ----------------
__device__ __forceinline__ u64 pack2(float x) {
    unsigned u = __float_as_uint(x);
    u64 r;
    asm("mov.b64 %0, {%1, %2};" : "=l"(r) : "r"(u), "r"(u));
    return r;
}
__device__ __forceinline__ u64 ffma2(u64 a, u64 b, u64 c) {
    u64 d;
    asm("fma.rn.f32x2 %0, %1, %2, %3;" : "=l"(d) : "l"(a), "l"(b), "l"(c));
    return d;
}
__device__ __forceinline__ void unpack2(u64 v, float& lo, float& hi) {
    unsigned a, b;
    asm("mov.b64 {%0, %1}, %2;" : "=r"(a), "=r"(b) : "l"(v));
    lo = __uint_as_float(a); hi = __uint_as_float(b);
}
__device__ __forceinline__ float sigmoidf_(float x) { return 1.f / (1.f + expf(-x)); }

// ---------------- weight transpose/prep (+ stats zeroing): [cout][cin][k] -> [cin*9+k][cout] --
__global__ void prep_weights(const float* __restrict__ we1, const float* __restrict__ we2,
                             const float* __restrict__ wf,  const float* __restrict__ wi,
                             const float* __restrict__ wc,  const float* __restrict__ wo,
                             const float* __restrict__ wr1, const float* __restrict__ wr2)
{
    int idx = blockIdx.x * 256 + threadIdx.x;
    if (idx < 512) g_stats[idx] = 0.f;
    if (idx < 1152) {
        int cout = idx % 32, t = idx / 32, k = t % 9, cin = t / 9;
        g_wt_e1[idx] = we1[cout*4*9 + cin*9 + k];
        return;
    }
    idx -= 1152;
    if (idx < 9216) {
        int cout = idx % 32, t = idx / 32, k = t % 9, cin = t / 9;
        g_wt_e2[idx] = we2[cout*32*9 + cin*9 + k];
        return;
    }
    idx -= 9216;
    if (idx < 4*18432) {
        int g = idx / 18432, d = idx % 18432;
        int cout = d % 32, t = d / 32, k = t % 9, cin = t / 9;
        const float* src = (g == 0) ? wf : (g == 1) ? wi : (g == 2) ? wc : wo;
        g_wt_g[idx] = src[cout*64*9 + cin*9 + k];
        return;
    }
    idx -= 4*18432;
    if (idx < 9216) {
        int cout = idx % 32, t = idx / 32, k = t % 9, cin = t / 9;
        g_wt_r1[idx] = wr1[cout*32*9 + cin*9 + k];
        return;
    }
    idx -= 9216;
    if (idx < 1152) {
        int cout = idx % 4, t = idx / 4, k = t % 9, cin = t / 9;
        g_wt_r2[idx] = (cout < 3) ? wr2[cout*32*9 + cin*9 + k] : 0.f;
        return;
    }
}

// stats (sum, sumsq) -> params (scale, bias): y = x*scale + bias == (x-mean)*rsqrt(var+eps)
__global__ void make_params(const float* __restrict__ stats, float2* __restrict__ params,
                            int nch, float invn)
{
    int c = threadIdx.x;
    if (c >= nch) return;
    float m   = stats[2*c] * invn;
    float var = stats[2*c+1] * invn - m * m;
    float sc  = rsqrtf(var + 1e-5f);
    params[c] = make_float2(sc, -m * sc);
}

// ---------------- generic 3x3 conv, f32x2 accumulators, fused input-BN + output-stats --------
// Block 16x16 threads, output tile 32x16 (2 px/thread: x and x+16).
// smem: weights [CIN*9][COUT], then CHUNK input tiles (TH+2)x(TW+2).
template<int CIN, int COUT, int CHUNK>
__global__ void __launch_bounds__(256)
conv3x3_v2(const float* __restrict__ inA, const float* __restrict__ inB, int csplit,
           const float2* __restrict__ prmA, const float2* __restrict__ prmB,
           int reluA, int reluB,
           const float* __restrict__ wt, float* __restrict__ out, float* __restrict__ statsOut,
           int H, int W, int pad, int HO, int WO)
{
    constexpr int TW = 32, TH = 16, TPW = TW + 2, TPH = TH + 2;
    constexpr int C2 = COUT / 2;
    static_assert(C2 % 2 == 0, "C2 must be even for 128b weight loads");
    extern __shared__ float smem[];
    float* ws   = smem;                         // CIN*9*COUT
    float* tile = smem + CIN*9*COUT;            // CHUNK * TPH*TPW
    __shared__ float sstat[2*COUT];

    const int tx = threadIdx.x, ty = threadIdx.y;
    const int tid = ty * 16 + tx;

    const float* wsrc = wt + (size_t)blockIdx.z * (CIN*9*COUT);
    for (int i = tid; i < CIN*9*COUT; i += 256) ws[i] = wsrc[i];
    if (tid < 2*COUT) sstat[tid] = 0.f;

    const int gx = blockIdx.x * TW, gy = blockIdx.y * TH;
    const int oy = gy + ty;
    const int ox0 = gx + tx, ox1 = ox0 + 16;

    u64 accA[C2], accB[C2];
#pragma unroll
    for (int p = 0; p < C2; p++) { accA[p] = 0ull; accB[p] = 0ull; }

    for (int cb = 0; cb < CIN; cb += CHUNK) {
        __syncthreads();
        // fill CHUNK tiles (with per-channel BN applied on load)
        for (int cc = 0; cc < CHUNK; ++cc) {
            int cin = cb + cc;
            bool isA = cin < csplit;
            const float* ip = isA ? (inA + (size_t)cin * H * W)
                                  : (inB + (size_t)(cin - csplit) * H * W);
            const float2* prm = isA ? prmA : prmB;
            int pidx = isA ? cin : (cin - csplit);
            float sc = 1.f, bi = 0.f;
            int rl = isA ? reluA : reluB;
            if (prm) { float2 p = prm[pidx]; sc = p.x; bi = p.y; }
            float* tb = tile + cc * TPH * TPW;
            for (int i = tid; i < TPH * TPW; i += 256) {
                int r = i / TPW, c = i % TPW;
                int iy = gy - pad + r, ix = gx - pad + c;
                float v = 0.f;
                if (iy >= 0 && iy < H && ix >= 0 && ix < W) {
                    v = ip[(size_t)iy * W + ix];
                    v = v * sc + bi;
                    if (rl) v = fmaxf(v, 0.f);
                }
                tb[i] = v;
            }
        }
        __syncthreads();

        for (int cc = 0; cc < CHUNK; ++cc) {
            const float* tb = tile + cc * TPH * TPW;
            float a[9], b[9];
#pragma unroll
            for (int ky = 0; ky < 3; ky++)
#pragma unroll
                for (int kx = 0; kx < 3; kx++) {
                    a[ky*3+kx] = tb[(ty + ky) * TPW + tx + kx];
                    b[ky*3+kx] = tb[(ty + ky) * TPW + tx + 16 + kx];
                }
            const u64* w2 = (const u64*)(ws + (cb + cc) * 9 * COUT);
#pragma unroll
            for (int k = 0; k < 9; k++) {
                u64 va = pack2(a[k]);
                u64 vb = pack2(b[k]);
                const ulonglong2* w4 = (const ulonglong2*)(w2 + k * C2);
#pragma unroll
                for (int p2 = 0; p2 < C2/2; p2++) {
                    ulonglong2 w = w4[p2];
                    accA[2*p2  ] = ffma2(va, w.x, accA[2*p2  ]);
                    accB[2*p2  ] = ffma2(vb, w.x, accB[2*p2  ]);
                    accA[2*p2+1] = ffma2(va, w.y, accA[2*p2+1]);
                    accB[2*p2+1] = ffma2(vb, w.y, accB[2*p2+1]);
                }
            }
        }
    }

    // ---- epilogue: store + fused per-channel (sum, sumsq) ----
    float* ob = out + (size_t)blockIdx.z * COUT * HO * WO;
    float* so = statsOut + blockIdx.z * 2 * COUT;
    const bool vA = (oy < HO) && (ox0 < WO);
    const bool vB = (oy < HO) && (ox1 < WO);
    const size_t row = (size_t)oy * WO;
#pragma unroll
    for (int p = 0; p < C2; p++) {
        float a0, a1, b0, b1;
        unpack2(accA[p], a0, a1);
        unpack2(accB[p], b0, b1);
        if (vA) {
            ob[(size_t)(2*p  ) * HO * WO + row + ox0] = a0;
            ob[(size_t)(2*p+1) * HO * WO + row + ox0] = a1;
        }
        if (vB) {
            ob[(size_t)(2*p  ) * HO * WO + row + ox1] = b0;
            ob[(size_t)(2*p+1) * HO * WO + row + ox1] = b1;
        }
        float s0 = (vA ? a0 : 0.f) + (vB ? b0 : 0.f);
        float q0 = (vA ? a0*a0 : 0.f) + (vB ? b0*b0 : 0.f);
        float s1 = (vA ? a1 : 0.f) + (vB ? b1 : 0.f);
        float q1 = (vA ? a1*a1 : 0.f) + (vB ? b1*b1 : 0.f);
#pragma unroll
        for (int o = 16; o; o >>= 1) {
            s0 += __shfl_down_sync(0xFFFFFFFFu, s0, o);
            q0 += __shfl_down_sync(0xFFFFFFFFu, q0, o);
            s1 += __shfl_down_sync(0xFFFFFFFFu, s1, o);
            q1 += __shfl_down_sync(0xFFFFFFFFu, q1, o);
        }
        if ((tid & 31) == 0) {
            atomicAdd(&sstat[4*p  ], s0);
            atomicAdd(&sstat[4*p+1], q0);
            atomicAdd(&sstat[4*p+2], s1);
            atomicAdd(&sstat[4*p+3], q1);
        }
    }
    __syncthreads();
    if (tid < 2*COUT) atomicAdd(&so[tid], sstat[tid]);
}

// ---------------- LSTM elementwise (reads raw gates + BN params) ----------------
__global__ void lstm_kernel(const float* __restrict__ prev_c, const float2* __restrict__ prm,
                            float* __restrict__ out_c, float* __restrict__ out_h)
{
    int idx = blockIdx.x * 256 + threadIdx.x;   // over 32*HW
    int c = idx >> 18;                          // HW = 2^18
    const int CHW = 32 * HW;

    float g[4];
#pragma unroll
    for (int gi = 0; gi < 4; gi++) {
        float2 p = prm[gi*32 + c];
        g[gi] = g_graw[(size_t)gi * CHW + idx] * p.x + p.y;
    }
    float f  = sigmoidf_(g[0]);
    float it = sigmoidf_(g[1]);
    float ct = tanhf(g[2]);
    float ot = sigmoidf_(g[3]);
    float nc = prev_c[idx] * f + it * ct;
    out_c[idx] = nc;
    out_h[idx] = tanhf(nc) * ot;
}

// ---------------- patch gather + per-channel dot ----------------
__global__ void gather_kernel(const int* __restrict__ holes,
                              const float* __restrict__ woil, const float* __restrict__ boil,
                              const float* __restrict__ wwat, const float* __restrict__ bwat,
                              const float* __restrict__ wgas, const float* __restrict__ bgas,
                              const float2* __restrict__ prm,
                              float* __restrict__ res)
{
    int nidx = threadIdx.x;
    if (nidx >= 256) return;
    int hx = holes[2*nidx], hy = holes[2*nidx+1];
    const float* wv[3] = { woil, wwat, wgas };
    float bv[3] = { boil[0], bwat[0], bgas[0] };
    for (int c = 0; c < 3; c++) {
        float2 p = prm[c];
        float s = bv[c];
        for (int i = 0; i < 3; i++)
            for (int j = 0; j < 3; j++) {
                float v = g_r2raw[(size_t)c * HW2 + (size_t)(hx + 3 + i) * HOB + (hy + 3 + j)];
                s += wv[c][i*3+j] * (v * p.x + p.y);
            }
        res[nidx*3 + c] = s;
    }
}

// ---------------- launch ----------------
extern "C" void kernel_launch(void* const* d_in, const int* in_sizes, int n_in,
                              void* d_out, int out_size)
{
    const float* x      = (const float*)d_in[0];
    const float* prev_c = (const float*)d_in[1];
    const float* prev_h = (const float*)d_in[2];
    const int*   holes  = (const int*)d_in[3];
    const float* w_e1   = (const float*)d_in[4];
    const float* w_e2   = (const float*)d_in[5];
    const float* w_f    = (const float*)d_in[6];
    const float* w_i    = (const float*)d_in[7];
    const float* w_c    = (const float*)d_in[8];
    const float* w_o    = (const float*)d_in[9];
    const float* w_r1   = (const float*)d_in[10];
    const float* w_r2   = (const float*)d_in[11];
    const float* w_oil  = (const float*)d_in[12];
    const float* b_oil  = (const float*)d_in[13];
    const float* w_wat  = (const float*)d_in[14];
    const float* b_wat  = (const float*)d_in[15];
    const float* w_gas  = (const float*)d_in[16];
    const float* b_gas  = (const float*)d_in[17];
    float* out = (float*)d_out;

    float *t1raw, *t2raw, *graw, *r1raw, *r2raw;
    float *wt_e1, *wt_e2, *wt_g, *wt_r1, *wt_r2, *stats;
    float2 *params;
    cudaGetSymbolAddress((void**)&t1raw, g_t1raw);
    cudaGetSymbolAddress((void**)&t2raw, g_t2raw);
    cudaGetSymbolAddress((void**)&graw,  g_graw);
    cudaGetSymbolAddress((void**)&r1raw, g_r1raw);
    cudaGetSymbolAddress((void**)&r2raw, g_r2raw);
    cudaGetSymbolAddress((void**)&wt_e1, g_wt_e1);
    cudaGetSymbolAddress((void**)&wt_e2, g_wt_e2);
    cudaGetSymbolAddress((void**)&wt_g,  g_wt_g);
    cudaGetSymbolAddress((void**)&wt_r1, g_wt_r1);
    cudaGetSymbolAddress((void**)&wt_r2, g_wt_r2);
    cudaGetSymbolAddress((void**)&stats, g_stats);
    cudaGetSymbolAddress((void**)&params, g_params);

    const int SM_E1 = (4*9*32  + 4*18*34) * 4;     // 14400
    const int SM_32 = (32*9*32 + 8*18*34) * 4;     // 56448
    const int SM_G  = (64*9*32 + 8*18*34) * 4;     // 93312
    const int SM_R2 = (32*9*4  + 8*18*34) * 4;     // 24192
    cudaFuncSetAttribute((const void*)conv3x3_v2<4,32,4>,  cudaFuncAttributeMaxDynamicSharedMemorySize, SM_E1);
    cudaFuncSetAttribute((const void*)conv3x3_v2<32,32,8>, cudaFuncAttributeMaxDynamicSharedMemorySize, SM_32);
    cudaFuncSetAttribute((const void*)conv3x3_v2<64,32,8>, cudaFuncAttributeMaxDynamicSharedMemorySize, SM_G);
    cudaFuncSetAttribute((const void*)conv3x3_v2<32,4,8>,  cudaFuncAttributeMaxDynamicSharedMemorySize, SM_R2);

    dim3 thr(16, 16);
    dim3 grid512(512/32, 512/16, 1);       // 16 x 32
    dim3 gridG  (512/32, 512/16, 4);
    dim3 gridR2 ((HOB + 31)/32, (HOB + 15)/16, 1);   // 17 x 33

    // launch order arranged so the 6th launch (ncu -s 5 -c 1) is the gates conv
    prep_weights<<<(94464 + 255)/256, 256>>>(w_e1, w_e2, w_f, w_i, w_c, w_o, w_r1, w_r2);

    // e1: x (4ch, raw) -> t1raw (+stats)
    conv3x3_v2<4,32,4><<<grid512, thr, SM_E1>>>(x, x, 4, nullptr, nullptr, 0, 0,
                                                wt_e1, t1raw, stats + 0, 512, 512, 1, 512, 512);
    make_params<<<1, 32>>>(stats + 0, params + 0, 32, 1.f / (float)HW);

    // e2: relu(BN(t1raw)) -> t2raw (+stats)
    conv3x3_v2<32,32,8><<<grid512, thr, SM_32>>>(t1raw, t1raw, 32, params + 0, params + 0, 1, 1,
                                                 wt_e2, t2raw, stats + 64, 512, 512, 1, 512, 512);
    make_params<<<1, 32>>>(stats + 64, params + 32, 32, 1.f / (float)HW);

    // gates: [prev_h (raw) ; BN(t2raw)] -> graw (4 x 32ch over z) (+stats)  [profiled launch]
    conv3x3_v2<64,32,8><<<gridG, thr, SM_G>>>(prev_h, t2raw, 32, nullptr, params + 32, 0, 0,
                                              wt_g, graw, stats + 128, 512, 512, 1, 512, 512);
    make_params<<<1, 128>>>(stats + 128, params + 64, 128, 1.f / (float)HW);

    // LSTM -> out[0:32HW]=next_c, out[32HW:64HW]=next_h
    lstm_kernel<<<32*HW/256, 256>>>(prev_c, params + 64, out, out + 32*HW);

    // r1: next_h (raw) -> r1raw (+stats)
    conv3x3_v2<32,32,8><<<grid512, thr, SM_32>>>(out + 32*HW, out + 32*HW, 32, nullptr, nullptr, 0, 0,
                                                 wt_r1, r1raw, stats + 384, 512, 512, 1, 512, 512);
    make_params<<<1, 32>>>(stats + 384, params + 192, 32, 1.f / (float)HW);

    // r2: relu(BN(r1raw)) -> r2raw (3+1 ch @ 518x518, pad 4) (+stats)
    conv3x3_v2<32,4,8><<<gridR2, thr, SM_R2>>>(r1raw, r1raw, 32, params + 192, params + 192, 1, 1,
                                               wt_r2, r2raw, stats + 448, 512, 512, 4, HOB, HOB);
    make_params<<<1, 32>>>(stats + 448, params + 224, 4, 1.f / (float)HW2);

    // gather + dot -> out tail
    gather_kernel<<<1, 256>>>(holes, w_oil, b_oil, w_wat, b_wat, w_gas, b_gas, params + 224, out + 64*HW);
}

// round 4
// speedup vs baseline: 1.1123x; 1.0492x over previous
#include <cuda_runtime.h>

#define HPX 512
#define WPX 512
#define HW  (HPX*WPX)           // 262144 = 2^18
#define HOB 518                 // r2 output side (512 + 2*4 - 2)
#define HW2 (HOB*HOB)           // 268324

typedef unsigned long long u64;

// ---------------- device scratch (no cudaMalloc allowed) ----------------
__device__ float g_t1raw[32*HW];
__device__ float g_t2raw[32*HW];
__device__ float g_graw [128*HW];
__device__ float g_r1raw[32*HW];
__device__ float g_r2raw[4*HW2];
__device__ float g_wt_e1[4*9*32];
__device__ float g_wt_e2[32*9*32];
__device__ float g_wt_g [4*64*9*32];
__device__ float g_wt_r1[32*9*32];
__device__ float g_wt_r2[32*9*4];
__device__ float  g_stats[512];    // e1:[0,64) e2:[64,128) gates:[128,384) r1:[384,448) r2:[448,456)
__device__ float2 g_params[256];   // e1:0 e2:32 gates:64 r1:192 r2:224   (scale, bias)

// ---------------- f32x2 helpers ----------------
__device__ __forceinline__ u64 pack2(float x) {
    unsigned u = __float_as_uint(x);
    u64 r;
    asm("mov.b64 %0, {%1, %2};" : "=l"(r) : "r"(u), "r"(u));
    return r;
}
__device__ __forceinline__ u64 ffma2(u64 a, u64 b, u64 c) {
    u64 d;
    asm("fma.rn.f32x2 %0, %1, %2, %3;" : "=l"(d) : "l"(a), "l"(b), "l"(c));
    return d;
}
__device__ __forceinline__ void unpack2(u64 v, float& lo, float& hi) {
    unsigned a, b;
    asm("mov.b64 {%0, %1}, %2;" : "=r"(a), "=r"(b) : "l"(v));
    lo = __uint_as_float(a); hi = __uint_as_float(b);
}
__device__ __forceinline__ float sigmoidf_(float x) { return 1.f / (1.f + expf(-x)); }

// ---------------- weight transpose/prep (+ stats zeroing): [cout][cin][k] -> [cin*9+k][cout] --
__global__ void prep_weights(const float* __restrict__ we1, const float* __restrict__ we2,
                             const float* __restrict__ wf,  const float* __restrict__ wi,
                             const float* __restrict__ wc,  const float* __restrict__ wo,
                             const float* __restrict__ wr1, const float* __restrict__ wr2)
{
    int idx = blockIdx.x * 256 + threadIdx.x;
    if (idx < 512) g_stats[idx] = 0.f;
    if (idx < 1152) {
        int cout = idx % 32, t = idx / 32, k = t % 9, cin = t / 9;
        g_wt_e1[idx] = we1[cout*4*9 + cin*9 + k];
        return;
    }
    idx -= 1152;
    if (idx < 9216) {
        int cout = idx % 32, t = idx / 32, k = t % 9, cin = t / 9;
        g_wt_e2[idx] = we2[cout*32*9 + cin*9 + k];
        return;
    }
    idx -= 9216;
    if (idx < 4*18432) {
        int g = idx / 18432, d = idx % 18432;
        int cout = d % 32, t = d / 32, k = t % 9, cin = t / 9;
        const float* src = (g == 0) ? wf : (g == 1) ? wi : (g == 2) ? wc : wo;
        g_wt_g[idx] = src[cout*64*9 + cin*9 + k];
        return;
    }
    idx -= 4*18432;
    if (idx < 9216) {
        int cout = idx % 32, t = idx / 32, k = t % 9, cin = t / 9;
        g_wt_r1[idx] = wr1[cout*32*9 + cin*9 + k];
        return;
    }
    idx -= 9216;
    if (idx < 1152) {
        int cout = idx % 4, t = idx / 4, k = t % 9, cin = t / 9;
        g_wt_r2[idx] = (cout < 3) ? wr2[cout*32*9 + cin*9 + k] : 0.f;
        return;
    }
}

// stats (sum, sumsq) -> params (scale, bias): y = x*scale + bias == (x-mean)*rsqrt(var+eps)
__global__ void make_params(const float* __restrict__ stats, float2* __restrict__ params,
                            int nch, float invn)
{
    int c = threadIdx.x;
    if (c >= nch) return;
    float m   = stats[2*c] * invn;
    float var = stats[2*c+1] * invn - m * m;
    float sc  = rsqrtf(var + 1e-5f);
    params[c] = make_float2(sc, -m * sc);
}

// ---------------- generic 3x3 conv v3: cout split across warp-groups -------------------------
// 256 threads = 2 groups x 128 (16x8). Output tile 32x8; thread handles px (tx, tx+16) at row ty
// for COUT/2 output channels. Weights staged WSTAGE cin at a time.
template<int CIN, int COUT, int CHUNK, int WSTAGE>
__global__ void __launch_bounds__(256, 3)
conv3x3_v3(const float* __restrict__ inA, const float* __restrict__ inB, int csplit,
           const float2* __restrict__ prmA, const float2* __restrict__ prmB,
           int reluA, int reluB,
           const float* __restrict__ wt, float* __restrict__ out, float* __restrict__ statsOut,
           int H, int W, int pad, int HO, int WO)
{
    constexpr int TW = 32, TH = 8, TPW = TW + 2, TPH = TH + 2;
    constexpr int TSZ = TPW * TPH;              // 340
    constexpr int COUTG = COUT / 2;             // couts per group
    constexpr int C2G   = COUTG / 2;            // u64 accs per pixel
    constexpr int C2    = COUT / 2;             // u64 weights per k row
    extern __shared__ float smem[];
    float* ws   = smem;                         // WSTAGE*9*COUT
    float* tile = smem + WSTAGE*9*COUT;         // CHUNK * TSZ
    __shared__ float sstat[2*COUT];

    const int tid   = threadIdx.x;
    const int group = tid >> 7;
    const int tx    = tid & 15;
    const int ty    = (tid >> 4) & 7;

    if (tid < 2*COUT) sstat[tid] = 0.f;

    const int gx = blockIdx.x * TW, gy = blockIdx.y * TH;
    const int oy = gy + ty;
    const int ox0 = gx + tx, ox1 = ox0 + 16;
    const float* wsrc = wt + (size_t)blockIdx.z * (CIN*9*COUT);

    u64 accA[C2G], accB[C2G];
#pragma unroll
    for (int p = 0; p < C2G; p++) { accA[p] = 0ull; accB[p] = 0ull; }

    for (int wb = 0; wb < CIN; wb += WSTAGE) {
        __syncthreads();                         // prior compute done (ws + tile reads)
        for (int i = tid; i < WSTAGE*9*COUT; i += 256) ws[i] = wsrc[wb*9*COUT + i];

        for (int cb = wb; cb < wb + WSTAGE; cb += CHUNK) {
            if (cb != wb) __syncthreads();       // prior compute done (tile reads)
            // fill CHUNK tiles, BN applied on load
            for (int cc = 0; cc < CHUNK; ++cc) {
                int cin = cb + cc;
                bool isA = cin < csplit;
                const float* ip = isA ? (inA + (size_t)cin * H * W)
                                      : (inB + (size_t)(cin - csplit) * H * W);
                const float2* prm = isA ? prmA : prmB;
                int pidx = isA ? cin : (cin - csplit);
                float sc = 1.f, bi = 0.f;
                int rl = isA ? reluA : reluB;
                if (prm) { float2 p = prm[pidx]; sc = p.x; bi = p.y; }
                float* tb = tile + cc * TSZ;
                for (int i = tid; i < TSZ; i += 256) {
                    int r = i / TPW, c = i % TPW;
                    int iy = gy - pad + r, ix = gx - pad + c;
                    float v = 0.f;
                    if (iy >= 0 && iy < H && ix >= 0 && ix < W) {
                        v = ip[(size_t)iy * W + ix];
                        v = v * sc + bi;
                        if (rl) v = fmaxf(v, 0.f);
                    }
                    tb[i] = v;
                }
            }
            __syncthreads();                     // fill (and staged ws) visible

            for (int cc = 0; cc < CHUNK; ++cc) {
                const float* tb = tile + cc * TSZ;
                float a[9], b[9];
#pragma unroll
                for (int ky = 0; ky < 3; ky++)
#pragma unroll
                    for (int kx = 0; kx < 3; kx++) {
                        a[ky*3+kx] = tb[(ty + ky) * TPW + tx + kx];
                        b[ky*3+kx] = tb[(ty + ky) * TPW + tx + 16 + kx];
                    }
                const u64* wrow = (const u64*)(ws + (cb - wb + cc) * 9 * COUT) + group * C2G;
#pragma unroll
                for (int k = 0; k < 9; k++) {
                    u64 va = pack2(a[k]);
                    u64 vb = pack2(b[k]);
                    if constexpr (C2G >= 2) {
                        const ulonglong2* w4 = (const ulonglong2*)(wrow + (size_t)k * C2);
#pragma unroll
                        for (int p2 = 0; p2 < C2G/2; p2++) {
                            ulonglong2 w = w4[p2];
                            accA[2*p2  ] = ffma2(va, w.x, accA[2*p2  ]);
                            accB[2*p2  ] = ffma2(vb, w.x, accB[2*p2  ]);
                            accA[2*p2+1] = ffma2(va, w.y, accA[2*p2+1]);
                            accB[2*p2+1] = ffma2(vb, w.y, accB[2*p2+1]);
                        }
                    } else {
                        u64 w = wrow[(size_t)k * C2];
                        accA[0] = ffma2(va, w, accA[0]);
                        accB[0] = ffma2(vb, w, accB[0]);
                    }
                }
            }
        }
    }

    // ---- epilogue: store + fused per-channel (sum, sumsq) ----
    float* ob = out + (size_t)blockIdx.z * COUT * HO * WO;
    float* so = statsOut + blockIdx.z * 2 * COUT;
    const bool vA = (oy < HO) && (ox0 < WO);
    const bool vB = (oy < HO) && (ox1 < WO);
    const size_t row = (size_t)oy * WO;
#pragma unroll
    for (int p = 0; p < C2G; p++) {
        int c0 = group * COUTG + 2*p;
        float a0, a1, b0, b1;
        unpack2(accA[p], a0, a1);
        unpack2(accB[p], b0, b1);
        if (vA) {
            ob[(size_t)(c0  ) * HO * WO + row + ox0] = a0;
            ob[(size_t)(c0+1) * HO * WO + row + ox0] = a1;
        }
        if (vB) {
            ob[(size_t)(c0  ) * HO * WO + row + ox1] = b0;
            ob[(size_t)(c0+1) * HO * WO + row + ox1] = b1;
        }
        float s0 = (vA ? a0 : 0.f) + (vB ? b0 : 0.f);
        float q0 = (vA ? a0*a0 : 0.f) + (vB ? b0*b0 : 0.f);
        float s1 = (vA ? a1 : 0.f) + (vB ? b1 : 0.f);
        float q1 = (vA ? a1*a1 : 0.f) + (vB ? b1*b1 : 0.f);
#pragma unroll
        for (int o = 16; o; o >>= 1) {
            s0 += __shfl_down_sync(0xFFFFFFFFu, s0, o);
            q0 += __shfl_down_sync(0xFFFFFFFFu, q0, o);
            s1 += __shfl_down_sync(0xFFFFFFFFu, s1, o);
            q1 += __shfl_down_sync(0xFFFFFFFFu, q1, o);
        }
        if ((tid & 31) == 0) {
            atomicAdd(&sstat[2*c0  ], s0);
            atomicAdd(&sstat[2*c0+1], q0);
            atomicAdd(&sstat[2*c0+2], s1);
            atomicAdd(&sstat[2*c0+3], q1);
        }
    }
    __syncthreads();
    if (tid < 2*COUT) atomicAdd(&so[tid], sstat[tid]);
}

// ---------------- LSTM elementwise (reads raw gates + BN params) ----------------
__global__ void lstm_kernel(const float* __restrict__ prev_c, const float2* __restrict__ prm,
                            float* __restrict__ out_c, float* __restrict__ out_h)
{
    int idx = blockIdx.x * 256 + threadIdx.x;   // over 32*HW
    int c = idx >> 18;                          // HW = 2^18
    const int CHW = 32 * HW;

    float g[4];
#pragma unroll
    for (int gi = 0; gi < 4; gi++) {
        float2 p = prm[gi*32 + c];
        g[gi] = g_graw[(size_t)gi * CHW + idx] * p.x + p.y;
    }
    float f  = sigmoidf_(g[0]);
    float it = sigmoidf_(g[1]);
    float ct = tanhf(g[2]);
    float ot = sigmoidf_(g[3]);
    float nc = prev_c[idx] * f + it * ct;
    out_c[idx] = nc;
    out_h[idx] = tanhf(nc) * ot;
}

// ---------------- patch gather + per-channel dot ----------------
__global__ void gather_kernel(const int* __restrict__ holes,
                              const float* __restrict__ woil, const float* __restrict__ boil,
                              const float* __restrict__ wwat, const float* __restrict__ bwat,
                              const float* __restrict__ wgas, const float* __restrict__ bgas,
                              const float2* __restrict__ prm,
                              float* __restrict__ res)
{
    int nidx = threadIdx.x;
    if (nidx >= 256) return;
    int hx = holes[2*nidx], hy = holes[2*nidx+1];
    const float* wv[3] = { woil, wwat, wgas };
    float bv[3] = { boil[0], bwat[0], bgas[0] };
    for (int c = 0; c < 3; c++) {
        float2 p = prm[c];
        float s = bv[c];
        for (int i = 0; i < 3; i++)
            for (int j = 0; j < 3; j++) {
                float v = g_r2raw[(size_t)c * HW2 + (size_t)(hx + 3 + i) * HOB + (hy + 3 + j)];
                s += wv[c][i*3+j] * (v * p.x + p.y);
            }
        res[nidx*3 + c] = s;
    }
}

// ---------------- launch ----------------
extern "C" void kernel_launch(void* const* d_in, const int* in_sizes, int n_in,
                              void* d_out, int out_size)
{
    const float* x      = (const float*)d_in[0];
    const float* prev_c = (const float*)d_in[1];
    const float* prev_h = (const float*)d_in[2];
    const int*   holes  = (const int*)d_in[3];
    const float* w_e1   = (const float*)d_in[4];
    const float* w_e2   = (const float*)d_in[5];
    const float* w_f    = (const float*)d_in[6];
    const float* w_i    = (const float*)d_in[7];
    const float* w_c    = (const float*)d_in[8];
    const float* w_o    = (const float*)d_in[9];
    const float* w_r1   = (const float*)d_in[10];
    const float* w_r2   = (const float*)d_in[11];
    const float* w_oil  = (const float*)d_in[12];
    const float* b_oil  = (const float*)d_in[13];
    const float* w_wat  = (const float*)d_in[14];
    const float* b_wat  = (const float*)d_in[15];
    const float* w_gas  = (const float*)d_in[16];
    const float* b_gas  = (const float*)d_in[17];
    float* out = (float*)d_out;

    float *t1raw, *t2raw, *graw, *r1raw, *r2raw;
    float *wt_e1, *wt_e2, *wt_g, *wt_r1, *wt_r2, *stats;
    float2 *params;
    cudaGetSymbolAddress((void**)&t1raw, g_t1raw);
    cudaGetSymbolAddress((void**)&t2raw, g_t2raw);
    cudaGetSymbolAddress((void**)&graw,  g_graw);
    cudaGetSymbolAddress((void**)&r1raw, g_r1raw);
    cudaGetSymbolAddress((void**)&r2raw, g_r2raw);
    cudaGetSymbolAddress((void**)&wt_e1, g_wt_e1);
    cudaGetSymbolAddress((void**)&wt_e2, g_wt_e2);
    cudaGetSymbolAddress((void**)&wt_g,  g_wt_g);
    cudaGetSymbolAddress((void**)&wt_r1, g_wt_r1);
    cudaGetSymbolAddress((void**)&wt_r2, g_wt_r2);
    cudaGetSymbolAddress((void**)&stats, g_stats);
    cudaGetSymbolAddress((void**)&params, g_params);

    constexpr int TSZ = 34 * 10;
    const int SM_E1 = (4*9*32  + 4*TSZ) * 4;
    const int SM_32 = (32*9*32 + 8*TSZ) * 4;
    const int SM_G  = (32*9*32 + 8*TSZ) * 4;     // staged weights (WSTAGE=32)
    const int SM_R2 = (32*9*4  + 8*TSZ) * 4;
    cudaFuncSetAttribute((const void*)conv3x3_v3<4,32,4,4>,   cudaFuncAttributeMaxDynamicSharedMemorySize, SM_E1);
    cudaFuncSetAttribute((const void*)conv3x3_v3<32,32,8,32>, cudaFuncAttributeMaxDynamicSharedMemorySize, SM_32);
    cudaFuncSetAttribute((const void*)conv3x3_v3<64,32,8,32>, cudaFuncAttributeMaxDynamicSharedMemorySize, SM_G);
    cudaFuncSetAttribute((const void*)conv3x3_v3<32,4,8,32>,  cudaFuncAttributeMaxDynamicSharedMemorySize, SM_R2);

    dim3 thr(256);
    dim3 grid512(512/32, 512/8, 1);        // 16 x 64
    dim3 gridG  (512/32, 512/8, 4);
    dim3 gridR2 ((HOB + 31)/32, (HOB + 7)/8, 1);   // 17 x 65

    // launch order arranged so the 6th launch (ncu -s 5 -c 1) is the gates conv
    prep_weights<<<(94464 + 255)/256, 256>>>(w_e1, w_e2, w_f, w_i, w_c, w_o, w_r1, w_r2);

    // e1: x (4ch, raw) -> t1raw (+stats)
    conv3x3_v3<4,32,4,4><<<grid512, thr, SM_E1>>>(x, x, 4, nullptr, nullptr, 0, 0,
                                                  wt_e1, t1raw, stats + 0, 512, 512, 1, 512, 512);
    make_params<<<1, 32>>>(stats + 0, params + 0, 32, 1.f / (float)HW);

    // e2: relu(BN(t1raw)) -> t2raw (+stats)
    conv3x3_v3<32,32,8,32><<<grid512, thr, SM_32>>>(t1raw, t1raw, 32, params + 0, params + 0, 1, 1,
                                                    wt_e2, t2raw, stats + 64, 512, 512, 1, 512, 512);
    make_params<<<1, 32>>>(stats + 64, params + 32, 32, 1.f / (float)HW);

    // gates: [prev_h (raw) ; BN(t2raw)] -> graw (4 x 32ch over z) (+stats)  [profiled launch]
    conv3x3_v3<64,32,8,32><<<gridG, thr, SM_G>>>(prev_h, t2raw, 32, nullptr, params + 32, 0, 0,
                                                 wt_g, graw, stats + 128, 512, 512, 1, 512, 512);
    make_params<<<1, 128>>>(stats + 128, params + 64, 128, 1.f / (float)HW);

    // LSTM -> out[0:32HW]=next_c, out[32HW:64HW]=next_h
    lstm_kernel<<<32*HW/256, 256>>>(prev_c, params + 64, out, out + 32*HW);

    // r1: next_h (raw) -> r1raw (+stats)
    conv3x3_v3<32,32,8,32><<<grid512, thr, SM_32>>>(out + 32*HW, out + 32*HW, 32, nullptr, nullptr, 0, 0,
                                                    wt_r1, r1raw, stats + 384, 512, 512, 1, 512, 512);
    make_params<<<1, 32>>>(stats + 384, params + 192, 32, 1.f / (float)HW);

    // r2: relu(BN(r1raw)) -> r2raw (3+1 ch @ 518x518, pad 4) (+stats)
    conv3x3_v3<32,4,8,32><<<gridR2, thr, SM_R2>>>(r1raw, r1raw, 32, params + 192, params + 192, 1, 1,
                                                  wt_r2, r2raw, stats + 448, 512, 512, 4, HOB, HOB);
    make_params<<<1, 32>>>(stats + 448, params + 224, 4, 1.f / (float)HW2);

    // gather + dot -> out tail
    gather_kernel<<<1, 256>>>(holes, w_oil, b_oil, w_wat, b_wat, w_gas, b_gas, params + 224, out + 64*HW);
}